// round 2
// baseline (speedup 1.0000x reference)
#include <cuda_runtime.h>
#include <cstdint>

// Elementwise: out[i] = x[i] + 42.0f  for 8192*4096 fp32 elements.
// Pure HBM-streaming kernel: float4 vectorized, x4 unrolled grid-stride.

__global__ void __launch_bounds__(256) add42_vec4(const float4* __restrict__ in,
                                                  float4* __restrict__ out,
                                                  long long n4) {
    const long long stride = (long long)gridDim.x * blockDim.x;
    long long i = (long long)blockIdx.x * blockDim.x + threadIdx.x;

    // Unroll x4: batch 4 independent 128-bit loads up front (MLP) before stores.
    #pragma unroll 1
    for (; i + 3 * stride < n4; i += 4 * stride) {
        float4 a = in[i];
        float4 b = in[i + stride];
        float4 c = in[i + 2 * stride];
        float4 d = in[i + 3 * stride];
        a.x += 42.0f; a.y += 42.0f; a.z += 42.0f; a.w += 42.0f;
        b.x += 42.0f; b.y += 42.0f; b.z += 42.0f; b.w += 42.0f;
        c.x += 42.0f; c.y += 42.0f; c.z += 42.0f; c.w += 42.0f;
        d.x += 42.0f; d.y += 42.0f; d.z += 42.0f; d.w += 42.0f;
        out[i] = a;
        out[i + stride] = b;
        out[i + 2 * stride] = c;
        out[i + 3 * stride] = d;
    }
    // Remainder float4s
    for (; i < n4; i += stride) {
        float4 a = in[i];
        a.x += 42.0f; a.y += 42.0f; a.z += 42.0f; a.w += 42.0f;
        out[i] = a;
    }
}

// Scalar tail for element counts not divisible by 4 (not hit for 8192*4096,
// but keeps the kernel general/correct).
__global__ void add42_tail(const float* __restrict__ in,
                           float* __restrict__ out,
                           long long start, long long n) {
    long long i = start + (long long)blockIdx.x * blockDim.x + threadIdx.x;
    if (i < n) out[i] = in[i] + 42.0f;
}

extern "C" void kernel_launch(void* const* d_in, const int* in_sizes, int n_in,
                              void* d_out, int out_size) {
    const float* x = (const float*)d_in[0];
    float* out = (float*)d_out;
    const long long n = (long long)in_sizes[0];

    const long long n4 = n / 4;
    if (n4 > 0) {
        const int threads = 256;
        // Size grid so each thread does ~4 float4s in one unrolled pass:
        // total work items = n4, per-iteration coverage = grid*threads*4.
        long long want_blocks = (n4 + (long long)threads * 4 - 1) / ((long long)threads * 4);
        // Cap grid; grid-stride loop covers the rest. 148 SMs * 16 CTAs is plenty.
        int blocks = (int)(want_blocks < 148LL * 16 ? want_blocks : 148LL * 16);
        if (blocks < 1) blocks = 1;
        add42_vec4<<<blocks, threads>>>((const float4*)x, (float4*)out, n4);
    }

    const long long tail_start = n4 * 4;
    const long long tail = n - tail_start;
    if (tail > 0) {
        int threads = 128;
        int blocks = (int)((tail + threads - 1) / threads);
        add42_tail<<<blocks, threads>>>(x, out, tail_start, n);
    }
}

// round 3
// speedup vs baseline: 1.0468x; 1.0468x over previous
#include <cuda_runtime.h>
#include <cstdint>

// out[i] = x[i] + 42.0f, 8192*4096 fp32. Pure HBM stream.
// Exact-tile kernel: each thread handles UNR float4s, all loads batched
// up front (MLP=8), streaming cache hints, no grid-stride loop.

constexpr int TPB = 256;
constexpr int UNR = 8;                       // float4 per thread
constexpr int TILE = TPB * UNR;              // float4 per block = 2048

__global__ void __launch_bounds__(TPB) add42_exact(const float4* __restrict__ in,
                                                   float4* __restrict__ out) {
    const unsigned base = blockIdx.x * TILE + threadIdx.x;
    float4 v[UNR];
    #pragma unroll
    for (int k = 0; k < UNR; k++)
        v[k] = __ldcs(&in[base + k * TPB]);   // evict-first: no reuse
    #pragma unroll
    for (int k = 0; k < UNR; k++) {
        v[k].x += 42.0f; v[k].y += 42.0f; v[k].z += 42.0f; v[k].w += 42.0f;
        __stcs(&out[base + k * TPB], v[k]);   // streaming store
    }
}

// Generic fallback (grid-stride, handles any n4 remainder after exact tiles).
__global__ void __launch_bounds__(TPB) add42_vec4_gs(const float4* __restrict__ in,
                                                     float4* __restrict__ out,
                                                     long long start, long long n4) {
    const long long stride = (long long)gridDim.x * blockDim.x;
    for (long long i = start + (long long)blockIdx.x * blockDim.x + threadIdx.x;
         i < n4; i += stride) {
        float4 a = __ldcs(&in[i]);
        a.x += 42.0f; a.y += 42.0f; a.z += 42.0f; a.w += 42.0f;
        __stcs(&out[i], a);
    }
}

__global__ void add42_tail(const float* __restrict__ in, float* __restrict__ out,
                           long long start, long long n) {
    long long i = start + (long long)blockIdx.x * blockDim.x + threadIdx.x;
    if (i < n) out[i] = in[i] + 42.0f;
}

extern "C" void kernel_launch(void* const* d_in, const int* in_sizes, int n_in,
                              void* d_out, int out_size) {
    const float* x = (const float*)d_in[0];
    float* out = (float*)d_out;
    const long long n = (long long)in_sizes[0];

    const long long n4 = n / 4;
    const long long exact_blocks = n4 / TILE;           // 4096 for 8192x4096
    if (exact_blocks > 0) {
        add42_exact<<<(int)exact_blocks, TPB>>>((const float4*)x, (float4*)out);
    }
    const long long vec_rem_start = exact_blocks * (long long)TILE;
    if (vec_rem_start < n4) {
        long long rem = n4 - vec_rem_start;
        int blocks = (int)((rem + TPB - 1) / TPB);
        if (blocks > 152 * 8) blocks = 152 * 8;
        add42_vec4_gs<<<blocks, TPB>>>((const float4*)x, (float4*)out,
                                       vec_rem_start, n4);
    }
    const long long tail_start = n4 * 4;
    if (tail_start < n) {
        long long tail = n - tail_start;
        int blocks = (int)((tail + 127) / 128);
        add42_tail<<<blocks, 128>>>(x, out, tail_start, n);
    }
}